// round 1
// baseline (speedup 1.0000x reference)
#include <cuda_runtime.h>
#include <math.h>

// Problem constants (match reference)
#define N_INPUTSC 2048
#define UNITSC    2048
#define LC        8
#define FANINC    4096
#define TOTALC    18432

// Tiling: per layer, grid = JT*KC GEMV blocks + JT materialization blocks
#define KC      64      // number of k-chunks
#define KCH     64      // chunk size = FANIN / KC
#define THREADS 256
#define JT      2       // j tiles
#define JPB     1024    // columns per block (256 threads * float4)

// Persistent scratch (allocation-free rule: __device__ globals)
__device__ float g_partial[2][KC * UNITSC];  // ping-pong partial sums, 512KB each
__device__ float g_outputs[TOTALC];          // materialized state vector

// Reduce one column of the previous layer's partial sums (+bias)
__device__ __forceinline__ float reduce_col(const float* __restrict__ P, float b, int u) {
    float s = b;
#pragma unroll 8
    for (int c = 0; c < KC; ++c) s += P[c * UNITSC + u];
    return s;
}

__global__ __launch_bounds__(THREADS) void layer_kernel(
    int layer,
    const float* __restrict__ x,
    const int*   __restrict__ node_inds,
    const float* __restrict__ Ws,
    const float* __restrict__ bs)
{
    const float* Pprev = g_partial[(layer + 1) & 1];  // == (layer-1)&1 for layer>=1
    float*       Pcur  = g_partial[layer & 1];
    const float* bprev = bs + (layer - 1) * UNITSC;   // only read when layer>=1
    const int limit = (layer + 1) << 11;              // slices > layer read as 0
    const int base  = layer << 11;                    // start of latest slice
    const int tid = threadIdx.x;

    if (blockIdx.x >= JT * KC) {
        // Materialization block: write slice `layer` (= x_layer) into g_outputs
        // so layers >= layer+2 can gather it directly.
        int jt = blockIdx.x - JT * KC;
        int j0 = jt * JPB + tid * 4;
        float4 o;
        if (layer == 0) {
            o = *reinterpret_cast<const float4*>(x + j0);
        } else {
            o.x = tanhf(reduce_col(Pprev, bprev[j0 + 0], j0 + 0));
            o.y = tanhf(reduce_col(Pprev, bprev[j0 + 1], j0 + 1));
            o.z = tanhf(reduce_col(Pprev, bprev[j0 + 2], j0 + 2));
            o.w = tanhf(reduce_col(Pprev, bprev[j0 + 3], j0 + 3));
        }
        *reinterpret_cast<float4*>(g_outputs + base + j0) = o;
        return;
    }

    __shared__ float sg[KCH];
    const int kc = blockIdx.x / JT;
    const int jt = blockIdx.x % JT;
    const int kb = kc * KCH;

    // Gather this block's k-chunk of the input vector.
    for (int k = tid; k < KCH; k += THREADS) {
        int idx = node_inds[layer * FANINC + kb + k];
        float v = 0.0f;
        if (idx < limit) {
            if (idx >= base) {
                // Latest slice: value not yet materialized -> reduce partials + tanh
                int u = idx & (UNITSC - 1);
                v = (layer == 0) ? x[u] : tanhf(reduce_col(Pprev, bprev[u], u));
            } else {
                v = g_outputs[idx];
            }
        }
        sg[k] = v;
    }
    __syncthreads();

    // GEMV partial: this block covers cols [jt*JPB, jt*JPB+JPB), rows [kb, kb+KCH)
    const float* W = Ws + ((size_t)layer * FANINC + kb) * UNITSC + jt * JPB + tid * 4;
    float ax = 0.f, ay = 0.f, az = 0.f, aw = 0.f;
#pragma unroll 8
    for (int k = 0; k < KCH; ++k) {
        float gk = sg[k];
        float4 w = *reinterpret_cast<const float4*>(W + (size_t)k * UNITSC);
        ax = fmaf(gk, w.x, ax);
        ay = fmaf(gk, w.y, ay);
        az = fmaf(gk, w.z, az);
        aw = fmaf(gk, w.w, aw);
    }
    float4 r = make_float4(ax, ay, az, aw);
    *reinterpret_cast<float4*>(Pcur + kc * UNITSC + jt * JPB + tid * 4) = r;
}

__global__ void finish_kernel(const float* __restrict__ bs, float* __restrict__ out) {
    int j = blockIdx.x * blockDim.x + threadIdx.x;  // 2048 threads total
    const float* P = g_partial[(LC - 1) & 1];
    float s = bs[(LC - 1) * UNITSC + j];
#pragma unroll 8
    for (int c = 0; c < KC; ++c) s += P[c * UNITSC + j];
    out[j] = tanhf(s);
}

extern "C" void kernel_launch(void* const* d_in, const int* in_sizes, int n_in,
                              void* d_out, int out_size) {
    const float* x  = (const float*)d_in[0];   // [2048] f32
    const int*   ni = (const int*)d_in[1];     // [8, 4096] i32
    const float* Ws = (const float*)d_in[2];   // [8, 4096, 2048] f32
    const float* bs = (const float*)d_in[3];   // [8, 2048] f32
    float* out = (float*)d_out;                // [2048] f32

    for (int i = 0; i < LC; ++i) {
        layer_kernel<<<JT * KC + JT, THREADS>>>(i, x, ni, Ws, bs);
    }
    finish_kernel<<<UNITSC / 256, 256>>>(bs, out);
}

// round 2
// speedup vs baseline: 1.0701x; 1.0701x over previous
#include <cuda_runtime.h>
#include <math.h>

// Problem constants (match reference)
#define N_INPUTSC 2048
#define UNITSC    2048
#define LC        8
#define FANINC    4096
#define TOTALC    18432

// Tiling: per layer, grid = KC*JT GEMV blocks + JT materialization blocks
#define KC      128     // number of k-chunks
#define KCH     32      // chunk size = FANIN / KC
#define THREADS 128
#define JT      4       // j tiles
#define JPB     512     // columns per block (128 threads * float4)

// Persistent scratch (allocation-free rule: __device__ globals)
__device__ float g_partial[2][KC * UNITSC];  // ping-pong partial sums, 1MB each
__device__ float g_outputs[TOTALC];          // materialized state vector

// Reduce one column of the previous layer's partial sums (+bias)
__device__ __forceinline__ float reduce_col(const float* __restrict__ P, float b, int u) {
    float s = b;
#pragma unroll 16
    for (int c = 0; c < KC; ++c) s += P[c * UNITSC + u];
    return s;
}

__global__ __launch_bounds__(THREADS, 1) void layer_kernel(
    int layer,
    const float* __restrict__ x,
    const int*   __restrict__ node_inds,
    const float* __restrict__ Ws,
    const float* __restrict__ bs)
{
    const float* Pprev = g_partial[(layer + 1) & 1];  // == (layer-1)&1 for layer>=1
    float*       Pcur  = g_partial[layer & 1];
    const float* bprev = bs + (layer - 1) * UNITSC;   // only read when layer>=1
    const int limit = (layer + 1) << 11;              // slices > layer read as 0
    const int base  = layer << 11;                    // start of latest slice
    const int tid = threadIdx.x;

    if (blockIdx.x >= JT * KC) {
        // Materialization block: write slice `layer` (= x_layer) into g_outputs
        // so layers >= layer+2 can gather it directly.
        int jt = blockIdx.x - JT * KC;
        int j0 = jt * JPB + tid * 4;
        float4 o;
        if (layer == 0) {
            o = *reinterpret_cast<const float4*>(x + j0);
        } else {
            o.x = tanhf(reduce_col(Pprev, bprev[j0 + 0], j0 + 0));
            o.y = tanhf(reduce_col(Pprev, bprev[j0 + 1], j0 + 1));
            o.z = tanhf(reduce_col(Pprev, bprev[j0 + 2], j0 + 2));
            o.w = tanhf(reduce_col(Pprev, bprev[j0 + 3], j0 + 3));
        }
        *reinterpret_cast<float4*>(g_outputs + base + j0) = o;
        return;
    }

    __shared__ float sg[KCH];
    const int kc = blockIdx.x / JT;
    const int jt = blockIdx.x % JT;
    const int kb = kc * KCH;

    // Gather this block's k-chunk of the input vector (threads 0..KCH-1).
    if (tid < KCH) {
        int k = tid;
        int idx = node_inds[layer * FANINC + kb + k];
        float v = 0.0f;
        if (idx < limit) {
            if (idx >= base) {
                // Latest slice: value not yet materialized -> reduce partials + tanh
                int u = idx & (UNITSC - 1);
                v = (layer == 0) ? x[u] : tanhf(reduce_col(Pprev, bprev[u], u));
            } else {
                v = g_outputs[idx];
            }
        }
        sg[k] = v;
    }
    __syncthreads();

    // GEMV partial: this block covers cols [jt*JPB, jt*JPB+JPB), rows [kb, kb+KCH)
    // Fully unrolled so ptxas software-pipelines many LDG.128 in flight.
    const float* W = Ws + ((size_t)layer * FANINC + kb) * UNITSC + jt * JPB + tid * 4;
    float ax = 0.f, ay = 0.f, az = 0.f, aw = 0.f;
#pragma unroll
    for (int k = 0; k < KCH; ++k) {
        float gk = sg[k];
        float4 w = *reinterpret_cast<const float4*>(W + (size_t)k * UNITSC);
        ax = fmaf(gk, w.x, ax);
        ay = fmaf(gk, w.y, ay);
        az = fmaf(gk, w.z, az);
        aw = fmaf(gk, w.w, aw);
    }
    float4 r = make_float4(ax, ay, az, aw);
    *reinterpret_cast<float4*>(Pcur + kc * UNITSC + jt * JPB + tid * 4) = r;
}

__global__ void finish_kernel(const float* __restrict__ bs, float* __restrict__ out) {
    int j = blockIdx.x * blockDim.x + threadIdx.x;  // 2048 threads total
    const float* P = g_partial[(LC - 1) & 1];
    float s = bs[(LC - 1) * UNITSC + j];
#pragma unroll 16
    for (int c = 0; c < KC; ++c) s += P[c * UNITSC + j];
    out[j] = tanhf(s);
}

extern "C" void kernel_launch(void* const* d_in, const int* in_sizes, int n_in,
                              void* d_out, int out_size) {
    const float* x  = (const float*)d_in[0];   // [2048] f32
    const int*   ni = (const int*)d_in[1];     // [8, 4096] i32
    const float* Ws = (const float*)d_in[2];   // [8, 4096, 2048] f32
    const float* bs = (const float*)d_in[3];   // [8, 2048] f32
    float* out = (float*)d_out;                // [2048] f32

    for (int i = 0; i < LC; ++i) {
        layer_kernel<<<JT * KC + JT, THREADS>>>(i, x, ni, Ws, bs);
    }
    finish_kernel<<<UNITSC / 256, 256>>>(bs, out);
}

// round 4
// speedup vs baseline: 1.7655x; 1.6499x over previous
#include <cuda_runtime.h>
#include <math.h>

// Problem constants (match reference)
#define N_INPUTSC 2048
#define UNITSC    2048
#define LC        8
#define FANINC    4096
#define TOTALC    18432

#define KC      128     // k-chunks (partial-sum depth)
#define KCH     32      // rows per chunk
#define JTILES  4       // column tiles of 512

// Persistent scratch (allocation-free rule: __device__ globals)
__device__ float g_partial[2][KC * UNITSC];  // ping-pong partials, 1MB each
__device__ float g_outputs[TOTALC];          // materialized state vector
__device__ float g_gather[FANINC];           // gathered input for current layer

// Warp-shuffle reduce of one column of the previous layer's partials.
__device__ __forceinline__ float warp_reduce_col(const float* __restrict__ P,
                                                 int u, int lane) {
    float s = 0.f;
#pragma unroll
    for (int j = 0; j < 4; ++j)
        s += P[(lane + 32 * j) * UNITSC + u];
#pragma unroll
    for (int off = 16; off; off >>= 1)
        s += __shfl_xor_sync(0xffffffffu, s, off);
    return s;
}

// ---------------------------------------------------------------------------
// prep: one warp per element. Warps 0..2047 materialize slice `layer` into
// g_outputs; warps 2048..6143 build the gathered vector g_gather.
// ---------------------------------------------------------------------------
__global__ __launch_bounds__(256) void prep_kernel(
    int layer,
    const float* __restrict__ x,
    const int*   __restrict__ node_inds,
    const float* __restrict__ bs)
{
    int gtid = blockIdx.x * 256 + threadIdx.x;
    int wid  = gtid >> 5;
    int lane = gtid & 31;
    const float* Pprev = g_partial[(layer + 1) & 1];
    const float* bprev = bs + (layer - 1) * UNITSC;
    const int base  = layer << 11;
    const int limit = base + UNITSC;

    if (wid < UNITSC) {
        int u = wid;
        float o;
        if (layer == 0) {
            o = x[u];
        } else {
            o = tanhf(warp_reduce_col(Pprev, u, lane) + bprev[u]);
        }
        if (lane == 0) g_outputs[base + u] = o;
    } else {
        int k = wid - UNITSC;
        int idx = node_inds[layer * FANINC + k];
        float v = 0.f;
        if (idx < base) {
            v = g_outputs[idx];           // older slice, already materialized
        } else if (idx < limit) {
            int u = idx - base;           // latest slice: recompute
            if (layer == 0) v = x[u];
            else            v = tanhf(warp_reduce_col(Pprev, u, lane) + bprev[u]);
        }
        if (lane == 0) g_gather[k] = v;
    }
}

// ---------------------------------------------------------------------------
// gemv: pure W streaming. 256-thread 1-D blocks, grid = KC * JTILES.
// Block (kc, jt): rows [kc*32, kc*32+32), cols [jt*512, jt*512+512).
// Thread: tx = tid&127 -> 4 cols (float4); tg = tid>>7 -> 16-row half.
// 16 independent LDG.128 per thread; two halves reduced through smem.
// ---------------------------------------------------------------------------
__global__ __launch_bounds__(256, 4) void gemv_kernel(
    int layer,
    const float* __restrict__ Ws)
{
    float* Pcur = g_partial[layer & 1];
    const int kc  = blockIdx.x >> 2;
    const int jt  = blockIdx.x & 3;
    const int tid = threadIdx.x;
    const int tx  = tid & 127;
    const int tg  = tid >> 7;

    __shared__ float  sg[KCH];
    __shared__ float4 red[128];

    if (tid < KCH) sg[tid] = g_gather[kc * KCH + tid];
    __syncthreads();

    const int j0 = jt * 512 + tx * 4;
    const float* W = Ws + ((size_t)layer * FANINC + kc * KCH + tg * 16) * UNITSC + j0;

    float ax = 0.f, ay = 0.f, az = 0.f, aw = 0.f;
#pragma unroll
    for (int r = 0; r < 16; ++r) {
        float gk = sg[tg * 16 + r];
        float4 w = *reinterpret_cast<const float4*>(W + (size_t)r * UNITSC);
        ax = fmaf(gk, w.x, ax);
        ay = fmaf(gk, w.y, ay);
        az = fmaf(gk, w.z, az);
        aw = fmaf(gk, w.w, aw);
    }

    if (tg == 1) red[tx] = make_float4(ax, ay, az, aw);
    __syncthreads();
    if (tg == 0) {
        float4 p = red[tx];
        ax += p.x; ay += p.y; az += p.z; aw += p.w;
        *reinterpret_cast<float4*>(Pcur + kc * UNITSC + j0) =
            make_float4(ax, ay, az, aw);
    }
}

// ---------------------------------------------------------------------------
// finish: reduce last layer's partials + bias + tanh -> d_out
// ---------------------------------------------------------------------------
__global__ __launch_bounds__(256) void finish_kernel(
    const float* __restrict__ bs, float* __restrict__ out)
{
    int gtid = blockIdx.x * 256 + threadIdx.x;
    int wid  = gtid >> 5;
    int lane = gtid & 31;
    const float* P = g_partial[(LC - 1) & 1];
    float s = warp_reduce_col(P, wid, lane);
    if (lane == 0) out[wid] = tanhf(s + bs[(LC - 1) * UNITSC + wid]);
}

extern "C" void kernel_launch(void* const* d_in, const int* in_sizes, int n_in,
                              void* d_out, int out_size) {
    const float* x  = (const float*)d_in[0];   // [2048] f32
    const int*   ni = (const int*)d_in[1];     // [8, 4096] i32
    const float* Ws = (const float*)d_in[2];   // [8, 4096, 2048] f32
    const float* bs = (const float*)d_in[3];   // [8, 2048] f32
    float* out = (float*)d_out;                // [2048] f32

    for (int i = 0; i < LC; ++i) {
        prep_kernel<<<(UNITSC + FANINC) / 8, 256>>>(i, x, ni, bs);
        gemv_kernel<<<KC * JTILES, 256>>>(i, Ws);
    }
    finish_kernel<<<UNITSC / 8, 256>>>(bs, out);
}